// round 2
// baseline (speedup 1.0000x reference)
#include <cuda_runtime.h>
#include <math.h>
#include <float.h>

#define N_SEQ 1536
#define NB    2
#define HEADS 8
#define DK    64
#define DV    192
#define DIM   1536
#define NPOS  (2*N_SEQ-1)      // 3071
#define FS    192
#define HDK   (HEADS*DK)       // 512
#define HDV   (HEADS*DV)       // 1536

// ---------------- static device scratch (no allocation allowed) ----------------
__device__ float g_pos [NPOS*FS];        // positional embeddings (3071 x 192)
__device__ float g_relk[NPOS*HDK];       // rel_k (3071 x 512)
__device__ float g_Q   [NB*N_SEQ*HDK];
__device__ float g_K   [NB*N_SEQ*HDK];
__device__ float g_V   [NB*N_SEQ*HDV];
__device__ float g_O   [NB*N_SEQ*HDV];

// correctly-rounded fp32 transcendentals (robust to --use_fast_math flag games)
__device__ __forceinline__ float logf_cr(float x)   { return (float)log((double)x); }
__device__ __forceinline__ float log1pf_cr(float x) { return (float)log1p((double)x); }
__device__ __forceinline__ float expf_cr(float x)   { return (float)exp((double)x); }

// XLA Lanczos lgamma, fp32, replicating xla::Lgamma op-for-op (input >= 0.5 path)
__device__ float lgamma_xla_f32(float input) {
    const float one_half = 0.5f;
    const float one = 1.0f;
    const float log_sqrt_two_pi = 0.91893853320467274178f;
    const float g_plus_half = 7.5f;
    const float log_g_plus_half = 2.01490302054226772453f;   // log(7.5)
    const float kBase = 0.99999999999980993227684700473478f;
    const float kCoef[8] = {
        676.520368121885098567009190444019f, -1259.13921672240287047156078755283f,
        771.3234287776530788486528258894f,   -176.61502916214059906584551354f,
        12.507343278686904814458936853f,     -0.13857109526572011689554707f,
        9.984369578019570859563e-6f,         1.50563273514931155834e-7f};
    float z = __fsub_rn(input, one);
    float x = kBase;
    #pragma unroll
    for (int i = 0; i < 8; i++) {
        float denom = __fadd_rn(__fadd_rn(z, (float)i), one);
        x = __fadd_rn(x, __fdiv_rn(kCoef[i], denom));
    }
    float t     = __fadd_rn(g_plus_half, z);
    float log_t = __fadd_rn(log_g_plus_half, log1pf_cr(__fdiv_rn(z, g_plus_half)));
    // log_y = log_sqrt_two_pi + (z + 0.5 - t/log_t) * log_t + log(x)
    float term  = __fmul_rn(__fsub_rn(__fadd_rn(z, one_half), __fdiv_rn(t, log_t)), log_t);
    return __fadd_rn(__fadd_rn(log_sqrt_two_pi, term), logf_cr(x));
}

// ---------------- positional embedding ----------------
// row p: dist = p-1535. layout: [exp(32), cm(32), gamma(32), sign*exp, sign*cm, sign*gamma]
__global__ void pos_embed_kernel() {
    int p = blockIdx.x;            // 0..3070
    int t = threadIdx.x;           // 0..95
    const double LN2 = 0.6931471805599453;
    double dist  = (double)(p - (N_SEQ - 1));
    double adist = fabs(dist);
    float  adist_f = (float)adist;
    float  sgn   = (p > N_SEQ-1) ? 1.f : ((p < N_SEQ-1) ? -1.f : 0.f);

    __shared__ float gprob[32];
    float val = 0.f;
    if (t < 32) {
        // exponential half-life features (insensitive -> double is fine)
        double max_range = log((double)N_SEQ) / LN2;      // log2(1536)
        double hl = exp2(3.0 + (double)t * (max_range - 3.0) / 31.0);
        val = (float)exp(-LN2 / hl * adist);
    } else if (t < 64) {
        int c = t - 32;
        double width = exp2((double)(c + 1)) - 1.0;
        val = (width > adist) ? 1.f : 0.f;
    } else {
        // gamma pdf features: replicate reference fp32 arithmetic exactly
        int c = t - 64;
        float mean = 48.f * (float)(c + 1);               // exact
        float cc   = __fdiv_rn(mean, 24.f);               // exact: 2(c+1)
        float conc = __fmul_rn(cc, cc);                   // exact
        float rate = __fdiv_rn(mean, 576.f);              // fp32 rounded
        float lg_a = logf_cr(adist_f);                    // -inf at adist=0
        // xlogy(conc-1, adist): x = conc-1 >= 3 (never 0) -> x*log(y), -inf at y=0
        float log_unnorm = __fsub_rn(__fmul_rn(__fsub_rn(conc, 1.f), lg_a),
                                     __fmul_rn(rate, adist_f));
        float log_norm   = __fsub_rn(lgamma_xla_f32(conc),
                                     __fmul_rn(conc, logf_cr(rate)));
        float prob = __fadd_rn(expf_cr(__fsub_rn(log_unnorm, log_norm)), 1e-8f);
        gprob[c] = prob;
    }
    __syncthreads();
    if (t >= 64) {
        float mx = gprob[0];
        #pragma unroll
        for (int i = 1; i < 32; i++) mx = fmaxf(mx, gprob[i]);
        val = __fdiv_rn(gprob[t - 64], mx);
    }
    g_pos[p*FS + t]      = val;
    g_pos[p*FS + 96 + t] = sgn * val;
}

// ---------------- generic SGEMM: C[M,N] = A[M,K] * B[N,K]^T (+bias) ----------------
// 128x128x8 tiles, 256 threads, 8x8 microtile. N must be a multiple of 128, K of 8.
template<bool BIAS>
__global__ __launch_bounds__(256) void sgemm_tn(const float* __restrict__ A,
                                                const float* __restrict__ B,
                                                const float* __restrict__ bias,
                                                float* __restrict__ C,
                                                int M, int N, int Kd) {
    __shared__ float As[8][128];
    __shared__ float Bs[8][128];
    int tid = threadIdx.x;
    int tx = tid & 15, ty = tid >> 4;
    int m0 = blockIdx.y * 128, n0 = blockIdx.x * 128;
    int lr = tid >> 1, lk = (tid & 1) * 4;
    float acc[8][8];
    #pragma unroll
    for (int i = 0; i < 8; i++)
        #pragma unroll
        for (int j = 0; j < 8; j++) acc[i][j] = 0.f;
    const float4 z4 = make_float4(0.f, 0.f, 0.f, 0.f);

    for (int k0 = 0; k0 < Kd; k0 += 8) {
        float4 a4 = (m0 + lr < M) ? *(const float4*)(A + (size_t)(m0 + lr)*Kd + k0 + lk) : z4;
        float4 b4 = (n0 + lr < N) ? *(const float4*)(B + (size_t)(n0 + lr)*Kd + k0 + lk) : z4;
        __syncthreads();
        As[lk+0][lr] = a4.x; As[lk+1][lr] = a4.y; As[lk+2][lr] = a4.z; As[lk+3][lr] = a4.w;
        Bs[lk+0][lr] = b4.x; Bs[lk+1][lr] = b4.y; Bs[lk+2][lr] = b4.z; Bs[lk+3][lr] = b4.w;
        __syncthreads();
        #pragma unroll
        for (int k = 0; k < 8; k++) {
            float ra[8], rb[8];
            *(float4*)(ra)   = *(const float4*)&As[k][ty*8];
            *(float4*)(ra+4) = *(const float4*)&As[k][ty*8+4];
            *(float4*)(rb)   = *(const float4*)&Bs[k][tx*8];
            *(float4*)(rb+4) = *(const float4*)&Bs[k][tx*8+4];
            #pragma unroll
            for (int i = 0; i < 8; i++)
                #pragma unroll
                for (int j = 0; j < 8; j++) acc[i][j] += ra[i] * rb[j];
        }
    }
    float bl[8];
    #pragma unroll
    for (int j = 0; j < 8; j++) bl[j] = BIAS ? bias[n0 + tx*8 + j] : 0.f;
    #pragma unroll
    for (int i = 0; i < 8; i++) {
        int row = m0 + ty*8 + i;
        if (row < M) {
            float4 c0, c1;
            c0.x = acc[i][0]+bl[0]; c0.y = acc[i][1]+bl[1]; c0.z = acc[i][2]+bl[2]; c0.w = acc[i][3]+bl[3];
            c1.x = acc[i][4]+bl[4]; c1.y = acc[i][5]+bl[5]; c1.z = acc[i][6]+bl[6]; c1.w = acc[i][7]+bl[7];
            *(float4*)(C + (size_t)row*N + n0 + tx*8)     = c0;
            *(float4*)(C + (size_t)row*N + n0 + tx*8 + 4) = c1;
        }
    }
}

// ---------------- fused attention (flash-style, fp32) ----------------
// relative_shift closed form: rel_logits[i,j] = qr_i . relk[j-i+n-1]
__global__ __launch_bounds__(256) void attn_kernel(const float* __restrict__ rcb,
                                                   const float* __restrict__ rpb) {
    extern __shared__ float sm[];
    float* qcs  = sm;               // [k*64 + i]  (k-major, 64x64)
    float* qrs  = qcs + 64*64;
    float* kts  = qrs + 64*64;      // [k*64 + j]
    float* rls  = kts + 64*64;      // [k*128 + p] p in [0,127)
    float* vss  = rls + 64*128;     // [j*192 + d]
    float* Ss   = vss + 64*192;     // [i*65 + j]
    float* mrow = Ss  + 64*65;
    float* lrow = mrow + 64;
    float* arow = lrow + 64;

    const int tid = threadIdx.x;
    const int bh  = blockIdx.y;
    const int bb  = bh >> 3, h = bh & 7;
    const int i0  = blockIdx.x * 64;
    const float scale = 0.125f;   // 64^-0.5

    // load q tile transposed, fold scale + biases
    {
        int row = tid >> 2;
        const float* qbase = g_Q + (size_t)(bb*N_SEQ + i0 + row)*HDK + h*DK;
        #pragma unroll
        for (int i = 0; i < 4; i++) {
            int kk = (tid & 3)*4 + i*16;
            float4 qv = *(const float4*)(qbase + kk);
            float4 cb = *(const float4*)(rcb + h*DK + kk);
            float4 pb = *(const float4*)(rpb + h*DK + kk);
            qcs[(kk+0)*64+row] = qv.x*scale + cb.x;
            qcs[(kk+1)*64+row] = qv.y*scale + cb.y;
            qcs[(kk+2)*64+row] = qv.z*scale + cb.z;
            qcs[(kk+3)*64+row] = qv.w*scale + cb.w;
            qrs[(kk+0)*64+row] = qv.x*scale + pb.x;
            qrs[(kk+1)*64+row] = qv.y*scale + pb.y;
            qrs[(kk+2)*64+row] = qv.z*scale + pb.z;
            qrs[(kk+3)*64+row] = qv.w*scale + pb.w;
        }
    }
    if (tid < 64) { mrow[tid] = -INFINITY; lrow[tid] = 0.f; }

    float accv[4][12];
    #pragma unroll
    for (int r = 0; r < 4; r++)
        #pragma unroll
        for (int d = 0; d < 12; d++) accv[r][d] = 0.f;
    const int prg = tid >> 4;     // row group: rows prg*4..+3
    const int pdg = tid & 15;     // dim group: dims pdg*12..+11

    for (int j0 = 0; j0 < N_SEQ; j0 += 64) {
        __syncthreads();
        // K tile transposed
        {
            int j = tid >> 2;
            const float* kbase = g_K + (size_t)(bb*N_SEQ + j0 + j)*HDK + h*DK;
            #pragma unroll
            for (int i = 0; i < 4; i++) {
                int kk = (tid & 3)*4 + i*16;
                float4 kv = *(const float4*)(kbase + kk);
                kts[(kk+0)*64+j] = kv.x; kts[(kk+1)*64+j] = kv.y;
                kts[(kk+2)*64+j] = kv.z; kts[(kk+3)*64+j] = kv.w;
            }
        }
        // V tile
        {
            #pragma unroll
            for (int it = 0; it < 12; it++) {
                int idx = tid + it*256;
                int jr = idx / 48, fp = idx % 48;
                float4 vv = *(const float4*)(g_V + (size_t)(bb*N_SEQ + j0 + jr)*HDV + h*DV + fp*4);
                *(float4*)(vss + jr*192 + fp*4) = vv;
            }
        }
        // rel_k tile transposed: rows p_global = j0-i0+1472+pl, pl in [0,127)
        {
            int pbase = j0 - i0 + 1472;
            #pragma unroll
            for (int it = 0; it < 8; it++) {
                int idx = tid + it*256;
                int pl = idx >> 4;
                int kk = (idx & 15)*4;
                if (pl < 127) {
                    float4 rv = *(const float4*)(g_relk + (size_t)(pbase + pl)*HDK + h*DK + kk);
                    rls[(kk+0)*128+pl] = rv.x; rls[(kk+1)*128+pl] = rv.y;
                    rls[(kk+2)*128+pl] = rv.z; rls[(kk+3)*128+pl] = rv.w;
                }
            }
        }
        __syncthreads();
        // S = qc.k^T + qr.relk[j-i+63]^T   (16x16 threads, 4x4 microtile)
        {
            int sx = tid & 15, sy = tid >> 4;
            float s[4][4];
            #pragma unroll
            for (int i = 0; i < 4; i++)
                #pragma unroll
                for (int j = 0; j < 4; j++) s[i][j] = 0.f;
            #pragma unroll 16
            for (int k = 0; k < 64; k++) {
                float a[4], q2[4], kb[4];
                *(float4*)a  = *(const float4*)&qcs[k*64 + sy*4];
                *(float4*)q2 = *(const float4*)&qrs[k*64 + sy*4];
                *(float4*)kb = *(const float4*)&kts[k*64 + sx*4];
                const float* rk = &rls[k*128 + sx*4 - sy*4 + 63];
                #pragma unroll
                for (int i = 0; i < 4; i++)
                    #pragma unroll
                    for (int j = 0; j < 4; j++)
                        s[i][j] += a[i]*kb[j] + q2[i]*rk[j - i];
            }
            #pragma unroll
            for (int i = 0; i < 4; i++)
                #pragma unroll
                for (int j = 0; j < 4; j++)
                    Ss[(sy*4+i)*65 + sx*4+j] = s[i][j];
        }
        __syncthreads();
        // online softmax update (4 threads per row)
        {
            int row = tid >> 2, part = tid & 3;
            float* srow = Ss + row*65 + part*16;
            float mloc = -INFINITY;
            #pragma unroll
            for (int c = 0; c < 16; c++) mloc = fmaxf(mloc, srow[c]);
            mloc = fmaxf(mloc, __shfl_xor_sync(0xffffffffu, mloc, 1));
            mloc = fmaxf(mloc, __shfl_xor_sync(0xffffffffu, mloc, 2));
            float mold = mrow[row];
            float mnew = fmaxf(mold, mloc);
            float sloc = 0.f;
            #pragma unroll
            for (int c = 0; c < 16; c++) { float e = __expf(srow[c] - mnew); srow[c] = e; sloc += e; }
            sloc += __shfl_xor_sync(0xffffffffu, sloc, 1);
            sloc += __shfl_xor_sync(0xffffffffu, sloc, 2);
            if (part == 0) {
                float al = __expf(mold - mnew);
                arow[row] = al;
                lrow[row] = lrow[row]*al + sloc;
                mrow[row] = mnew;
            }
        }
        __syncthreads();
        // PV accumulate (16 row groups x 16 dim groups)
        {
            float al[4];
            #pragma unroll
            for (int r = 0; r < 4; r++) al[r] = arow[prg*4 + r];
            #pragma unroll
            for (int r = 0; r < 4; r++)
                #pragma unroll
                for (int d = 0; d < 12; d++) accv[r][d] *= al[r];
            #pragma unroll 8
            for (int kk = 0; kk < 64; kk++) {
                float p[4];
                #pragma unroll
                for (int r = 0; r < 4; r++) p[r] = Ss[(prg*4+r)*65 + kk];
                float4 v0 = *(const float4*)&vss[kk*192 + pdg*12];
                float4 v1 = *(const float4*)&vss[kk*192 + pdg*12 + 4];
                float4 v2 = *(const float4*)&vss[kk*192 + pdg*12 + 8];
                #pragma unroll
                for (int r = 0; r < 4; r++) {
                    accv[r][0] += p[r]*v0.x; accv[r][1] += p[r]*v0.y;
                    accv[r][2] += p[r]*v0.z; accv[r][3] += p[r]*v0.w;
                    accv[r][4] += p[r]*v1.x; accv[r][5] += p[r]*v1.y;
                    accv[r][6] += p[r]*v1.z; accv[r][7] += p[r]*v1.w;
                    accv[r][8] += p[r]*v2.x; accv[r][9] += p[r]*v2.y;
                    accv[r][10] += p[r]*v2.z; accv[r][11] += p[r]*v2.w;
                }
            }
        }
    }
    __syncthreads();
    // epilogue: O[(b*n+i)][h*192 + d] = acc / l
    #pragma unroll
    for (int r = 0; r < 4; r++) {
        int i = i0 + prg*4 + r;
        float inv = 1.f / lrow[prg*4 + r];
        float* obase = g_O + (size_t)(bb*N_SEQ + i)*HDV + h*DV + pdg*12;
        float4 o0 = make_float4(accv[r][0]*inv, accv[r][1]*inv, accv[r][2]*inv, accv[r][3]*inv);
        float4 o1 = make_float4(accv[r][4]*inv, accv[r][5]*inv, accv[r][6]*inv, accv[r][7]*inv);
        float4 o2 = make_float4(accv[r][8]*inv, accv[r][9]*inv, accv[r][10]*inv, accv[r][11]*inv);
        *(float4*)(obase)     = o0;
        *(float4*)(obase + 4) = o1;
        *(float4*)(obase + 8) = o2;
    }
}

// ---------------- launch ----------------
extern "C" void kernel_launch(void* const* d_in, const int* in_sizes, int n_in,
                              void* d_out, int out_size) {
    const float* x    = (const float*)d_in[0];
    const float* Wq   = (const float*)d_in[1];
    const float* Wk   = (const float*)d_in[2];
    const float* Wv   = (const float*)d_in[3];
    const float* Wrel = (const float*)d_in[4];
    const float* Wout = (const float*)d_in[5];
    const float* bo   = (const float*)d_in[6];
    const float* rcb  = (const float*)d_in[7];
    const float* rpb  = (const float*)d_in[8];

    float *pos, *relk, *Qp, *Kp, *Vp, *Op;
    cudaGetSymbolAddress((void**)&pos,  g_pos);
    cudaGetSymbolAddress((void**)&relk, g_relk);
    cudaGetSymbolAddress((void**)&Qp,   g_Q);
    cudaGetSymbolAddress((void**)&Kp,   g_K);
    cudaGetSymbolAddress((void**)&Vp,   g_V);
    cudaGetSymbolAddress((void**)&Op,   g_O);

    // 1. positional embeddings
    pos_embed_kernel<<<NPOS, 96>>>();
    // 2. rel_k = pos @ Wrel^T                    (3071 x 512, K=192)
    sgemm_tn<false><<<dim3(HDK/128, (NPOS+127)/128), 256>>>(pos, Wrel, nullptr, relk, NPOS, HDK, FS);
    // 3. Q/K/V projections                       (3072 x {512,512,1536}, K=1536)
    sgemm_tn<false><<<dim3(HDK/128, (NB*N_SEQ)/128), 256>>>(x, Wq, nullptr, Qp, NB*N_SEQ, HDK, DIM);
    sgemm_tn<false><<<dim3(HDK/128, (NB*N_SEQ)/128), 256>>>(x, Wk, nullptr, Kp, NB*N_SEQ, HDK, DIM);
    sgemm_tn<false><<<dim3(HDV/128, (NB*N_SEQ)/128), 256>>>(x, Wv, nullptr, Vp, NB*N_SEQ, HDV, DIM);
    // 4. fused attention with relative shift
    int smem = (64*64*3 + 64*128 + 64*192 + 64*65 + 192) * (int)sizeof(float);
    cudaFuncSetAttribute(attn_kernel, cudaFuncAttributeMaxDynamicSharedMemorySize, smem);
    attn_kernel<<<dim3(N_SEQ/64, NB*HEADS), 256, smem>>>(rcb, rpb);
    // 5. output projection + bias -> d_out
    sgemm_tn<true><<<dim3(DIM/128, (NB*N_SEQ)/128), 256>>>(Op, Wout, bo, (float*)d_out, NB*N_SEQ, DIM, HDV);
}